// round 2
// baseline (speedup 1.0000x reference)
#include <cuda_runtime.h>
#include <math.h>

#define Nn 50000
#define Ee 600000
#define Dd 128

// Scratch (allocation-free rule: __device__ globals)
__device__ float g_m[Nn * Dd];     // per-node messages
__device__ float g_sum[Nn * Dd];   // scatter accumulation
__device__ float g_cnt[Nn];        // in-degree

// ---------------------------------------------------------------------------
// Zero the accumulators
// ---------------------------------------------------------------------------
__global__ void zero_kernel() {
    int i = blockIdx.x * blockDim.x + threadIdx.x;
    int stride = gridDim.x * blockDim.x;
    float4 z = make_float4(0.f, 0.f, 0.f, 0.f);
    for (int j = i; j < Nn * Dd / 4; j += stride)
        reinterpret_cast<float4*>(g_sum)[j] = z;
    for (int j = i; j < Nn; j += stride)
        g_cnt[j] = 0.f;
}

// ---------------------------------------------------------------------------
// Fused 2-layer MLP over [nrows,128] with input/output transforms.
// MODE 0: in = logmap0(x) (param X), out = g_m
// MODE 1: in = g_sum / (g_cnt + eps), out = expmap0(mlp(...)) -> param Out
//
// CTA: 128 rows, 256 threads (16x16), 8x8 register tile per thread.
// Dynamic smem: sW[128][128] + sA[128][129] + sH[128][129]  (~193 KB)
// sA/sH are k-major: buf[k*129 + r]
// ---------------------------------------------------------------------------
__device__ __forceinline__ void gemm_tile_8x8(const float* __restrict__ A,
                                              const float* __restrict__ W,
                                              int tx, int ty, float acc[8][8]) {
#pragma unroll 1
    for (int k = 0; k < 128; k++) {
        float a[8];
        const float* pA = A + k * 129 + (ty << 3);
#pragma unroll
        for (int i = 0; i < 8; i++) a[i] = pA[i];
        float4 w0 = *reinterpret_cast<const float4*>(W + k * 128 + (tx << 3));
        float4 w1 = *reinterpret_cast<const float4*>(W + k * 128 + (tx << 3) + 4);
        float w[8] = {w0.x, w0.y, w0.z, w0.w, w1.x, w1.y, w1.z, w1.w};
#pragma unroll
        for (int i = 0; i < 8; i++)
#pragma unroll
            for (int j = 0; j < 8; j++)
                acc[i][j] = fmaf(a[i], w[j], acc[i][j]);
    }
}

template <int MODE>
__global__ __launch_bounds__(256, 1) void mlp_kernel(
    const float* __restrict__ X,
    const float* __restrict__ W1, const float* __restrict__ B1,
    const float* __restrict__ W2, const float* __restrict__ B2,
    float* __restrict__ Out) {
    extern __shared__ float smem[];
    float* sW = smem;                      // [128][128]
    float* sA = smem + 128 * 128;          // [128][129]
    float* sH = sA + 128 * 129;            // [128][129]
    __shared__ float sB[128];

    const int tid = threadIdx.x;
    const int tx = tid & 15, ty = tid >> 4;
    const int row0 = blockIdx.x * 128;

    const float* Xin = (MODE == 0) ? X : (const float*)g_sum;
    float* Op = (MODE == 0) ? (float*)g_m : Out;

    // ---- stage W1, b1 ----
    {
        const float4* src = reinterpret_cast<const float4*>(W1);
        float4* dst = reinterpret_cast<float4*>(sW);
        for (int i = tid; i < 128 * 32; i += 256) dst[i] = src[i];
    }
    if (tid < 128) sB[tid] = B1[tid];

    // ---- load input block, apply input transform, store k-major ----
    {
        const int warp = tid >> 5, lane = tid & 31;
        for (int rr = warp; rr < 128; rr += 8) {
            const int r = row0 + rr;
            float4 v = make_float4(0.f, 0.f, 0.f, 0.f);
            if (r < Nn) {
                v = reinterpret_cast<const float4*>(Xin + (size_t)r * 128)[lane];
                if (MODE == 1) {
                    float inv = 1.f / (g_cnt[r] + 1e-8f);
                    v.x *= inv; v.y *= inv; v.z *= inv; v.w *= inv;
                }
            }
            if (MODE == 0) {
                float ss = v.x * v.x + v.y * v.y + v.z * v.z + v.w * v.w;
#pragma unroll
                for (int o = 16; o > 0; o >>= 1)
                    ss += __shfl_xor_sync(0xffffffffu, ss, o);
                float nrm = sqrtf(ss);
                float nc = fminf(fmaxf(nrm, 1e-8f), 1.f - 1e-5f);
                float f = atanhf(nc) / nc;
                v.x *= f; v.y *= f; v.z *= f; v.w *= f;
            }
            const int k0 = lane * 4;
            sA[(k0 + 0) * 129 + rr] = v.x;
            sA[(k0 + 1) * 129 + rr] = v.y;
            sA[(k0 + 2) * 129 + rr] = v.z;
            sA[(k0 + 3) * 129 + rr] = v.w;
        }
    }
    __syncthreads();

    // ---- phase 1: hidden = relu(A @ W1 + b1), store transposed into sH ----
    float acc[8][8];
#pragma unroll
    for (int i = 0; i < 8; i++)
#pragma unroll
        for (int j = 0; j < 8; j++) acc[i][j] = 0.f;

    gemm_tile_8x8(sA, sW, tx, ty, acc);

#pragma unroll
    for (int j = 0; j < 8; j++) {
        const int c = (tx << 3) + j;
        const float b = sB[c];
#pragma unroll
        for (int i = 0; i < 8; i++) {
            float v = fmaxf(acc[i][j] + b, 0.f);
            sH[c * 129 + (ty << 3) + i] = v;
        }
    }
    __syncthreads();

    // ---- stage W2, b2 ----
    {
        const float4* src = reinterpret_cast<const float4*>(W2);
        float4* dst = reinterpret_cast<float4*>(sW);
        for (int i = tid; i < 128 * 32; i += 256) dst[i] = src[i];
    }
    if (tid < 128) sB[tid] = B2[tid];
    __syncthreads();

    // ---- phase 2: out = H @ W2 + b2 ----
#pragma unroll
    for (int i = 0; i < 8; i++)
#pragma unroll
        for (int j = 0; j < 8; j++) acc[i][j] = 0.f;

    gemm_tile_8x8(sH, sW, tx, ty, acc);

#pragma unroll
    for (int j = 0; j < 8; j++) {
        const float b = sB[(tx << 3) + j];
#pragma unroll
        for (int i = 0; i < 8; i++) acc[i][j] += b;
    }

    if (MODE == 1) {
        // expmap0 per row: norm across 128 cols = reduce across the 16 tx
        // threads that share this row (they sit in the same warp half).
#pragma unroll
        for (int i = 0; i < 8; i++) {
            float ss = 0.f;
#pragma unroll
            for (int j = 0; j < 8; j++) ss += acc[i][j] * acc[i][j];
            ss += __shfl_xor_sync(0xffffffffu, ss, 1);
            ss += __shfl_xor_sync(0xffffffffu, ss, 2);
            ss += __shfl_xor_sync(0xffffffffu, ss, 4);
            ss += __shfl_xor_sync(0xffffffffu, ss, 8);
            float nrm = sqrtf(ss);
            float nc = fmaxf(nrm, 1e-8f);
            float f = tanhf(nc) / nc;
#pragma unroll
            for (int j = 0; j < 8; j++) acc[i][j] *= f;
        }
    }

    // ---- store ----
#pragma unroll
    for (int i = 0; i < 8; i++) {
        const int r = row0 + (ty << 3) + i;
        if (r < Nn) {
            float4 v0 = make_float4(acc[i][0], acc[i][1], acc[i][2], acc[i][3]);
            float4 v1 = make_float4(acc[i][4], acc[i][5], acc[i][6], acc[i][7]);
            float* p = Op + (size_t)r * 128 + (tx << 3);
            *reinterpret_cast<float4*>(p) = v0;
            *reinterpret_cast<float4*>(p + 4) = v1;
        }
    }
}

// ---------------------------------------------------------------------------
// Scatter: one warp per edge. g_sum[dst] += g_m[src]; g_cnt[dst] += 1.
// float4 RED (no-return atomic) per lane.
// ---------------------------------------------------------------------------
__global__ __launch_bounds__(256) void scatter_kernel(const int* __restrict__ ei) {
    const int gw = (blockIdx.x * blockDim.x + threadIdx.x) >> 5;
    const int lane = threadIdx.x & 31;
    if (gw >= Ee) return;
    const int dst = ei[gw];         // edge_index[0] = row
    const int src = ei[Ee + gw];    // edge_index[1] = col
    float4 v = reinterpret_cast<const float4*>(g_m + (size_t)src * 128)[lane];
    float* p = g_sum + (size_t)dst * 128 + lane * 4;
    asm volatile("red.global.add.v4.f32 [%0], {%1,%2,%3,%4};"
                 :: "l"(p), "f"(v.x), "f"(v.y), "f"(v.z), "f"(v.w)
                 : "memory");
    if (lane == 0) atomicAdd(&g_cnt[dst], 1.0f);
}

// ---------------------------------------------------------------------------
extern "C" void kernel_launch(void* const* d_in, const int* in_sizes, int n_in,
                              void* d_out, int out_size) {
    const float* x  = (const float*)d_in[0];
    const int*   ei = (const int*)d_in[1];
    const float* w1 = (const float*)d_in[2];
    const float* b1 = (const float*)d_in[3];
    const float* w2 = (const float*)d_in[4];
    const float* b2 = (const float*)d_in[5];
    const float* w3 = (const float*)d_in[6];
    const float* b3 = (const float*)d_in[7];
    const float* w4 = (const float*)d_in[8];
    const float* b4 = (const float*)d_in[9];
    float* out = (float*)d_out;

    const size_t shmem = (size_t)(128 * 128 + 2 * 128 * 129) * sizeof(float);
    cudaFuncSetAttribute(mlp_kernel<0>, cudaFuncAttributeMaxDynamicSharedMemorySize, (int)shmem);
    cudaFuncSetAttribute(mlp_kernel<1>, cudaFuncAttributeMaxDynamicSharedMemorySize, (int)shmem);

    const int mlp_blocks = (Nn + 127) / 128;  // 391

    zero_kernel<<<1024, 256>>>();
    mlp_kernel<0><<<mlp_blocks, 256, shmem>>>(x, w1, b1, w2, b2, nullptr);
    scatter_kernel<<<Ee / 8, 256>>>(ei);
    mlp_kernel<1><<<mlp_blocks, 256, shmem>>>(nullptr, w3, b3, w4, b4, out);
}